// round 6
// baseline (speedup 1.0000x reference)
#include <cuda_runtime.h>
#include <math.h>
#include <stdint.h>

#define Bb 128
#define Uu 16
#define Dd 256
#define Nn 1024
#define Oo 256
#define CAP 320
#define NCH 10

typedef unsigned long long ull;

__device__ float g_lr[Bb * Uu];
__device__ ull   g_ent[(size_t)Uu * Nn * CAP];   // packed (val<<32 | k)
__device__ int   g_cs[Uu * Nn * (NCH + 1)];      // per-column chunk offsets

// ---------------------------------------------------------------------------
// helpers
// ---------------------------------------------------------------------------
__device__ __forceinline__ ull pk2(float x) {
    ull r;
    asm("mov.b64 %0, {%1, %1};" : "=l"(r) : "f"(x));
    return r;
}
__device__ __forceinline__ ull fma2(ull a, ull b, ull c) {
    asm("fma.rn.f32x2 %0, %1, %2, %0;" : "+l"(c) : "l"(a), "l"(b));
    return c;
}
__device__ __forceinline__ float lo32(ull v) { return __uint_as_float((uint32_t)v); }
__device__ __forceinline__ float hi32(ull v) { return __uint_as_float((uint32_t)(v >> 32)); }

#define CP16(dst, src) \
    asm volatile("cp.async.cg.shared.global [%0], [%1], 16;" :: "r"(dst), "l"(src))
#define CPCOMMIT() asm volatile("cp.async.commit_group;" ::: "memory")
#define CPWAIT0()  asm volatile("cp.async.wait_group 0;" ::: "memory")

// ---------------------------------------------------------------------------
// Kernel 1: fused lr-softmax + sparse packing of [Win ; W] columns.
// grid = 128 blocks (u = blk>>3, m-tile = blk&7), 128 threads.
// lr part: block handles batch b = blockIdx.x.
// ---------------------------------------------------------------------------
__global__ __launch_bounds__(128) void prep_kernel(
    const float* __restrict__ X,
    const float* __restrict__ alr,
    const float* __restrict__ temp,
    const float* __restrict__ W,
    const float* __restrict__ Win)
{
    const int t = threadIdx.x;
    const int blk = blockIdx.x;
    __shared__ float logits[Uu];

    // ---- lr: b = blk; 8 threads per unit
    {
        const int b = blk;
        const int u = t >> 3;
        const int l8 = t & 7;
        const float* xp = X + (b * Uu + u) * Dd;
        const float* ap = alr + u * Dd;
        float s = 0.f;
        #pragma unroll
        for (int d = l8; d < Dd; d += 8) s += xp[d] * ap[d];
        s += __shfl_xor_sync(0xffffffffu, s, 1);
        s += __shfl_xor_sync(0xffffffffu, s, 2);
        s += __shfl_xor_sync(0xffffffffu, s, 4);
        if (l8 == 0) logits[u] = s / temp[0];
        __syncthreads();
        if (t == 0) {
            float m = -INFINITY;
            #pragma unroll
            for (int i = 0; i < Uu; i++) m = fmaxf(m, logits[i]);
            float e[Uu], denom = 0.f;
            #pragma unroll
            for (int i = 0; i < Uu; i++) { e[i] = __expf(logits[i] - m); denom += e[i]; }
            float inv = 1.f / denom;
            #pragma unroll
            for (int i = 0; i < Uu; i++) g_lr[b * Uu + i] = e[i] * inv;
        }
    }

    // ---- sparse packing: thread owns one column m of unit u
    const int u = blk >> 3;
    const int m = (blk & 7) * 128 + t;
    const int col = u * Nn + m;
    ull* ent = g_ent + (size_t)col * CAP;
    int* cs  = g_cs + col * (NCH + 1);

    int cnt = 0;
    cs[0] = 0;
    // Win region: k = 0..255 (chunks 0,1)
    #pragma unroll 4
    for (int k = 0; k < Dd; ++k) {
        if (k == 128) cs[1] = cnt;
        float v = Win[((size_t)u * Dd + k) * Nn + m];
        if (v != 0.f && cnt < CAP) {
            ent[cnt] = ((ull)__float_as_uint(v) << 32) | (uint32_t)k;
            cnt++;
        }
    }
    cs[2] = cnt;
    // W region: k = 256..1279 (chunks 2..9)
    #pragma unroll 4
    for (int kk = 0; kk < Nn; ++kk) {
        if (kk && (kk & 127) == 0) cs[2 + (kk >> 7)] = cnt;
        float v = W[((size_t)u * Nn + kk) * Nn + m];
        if (v != 0.f && cnt < CAP) {
            ent[cnt] = ((ull)__float_as_uint(v) << 32) | (uint32_t)(Dd + kk);
            cnt++;
        }
    }
    cs[NCH] = cnt;
}

// ---------------------------------------------------------------------------
// Kernel 2: sparse state update.
// Block (m-tile 128, u): acc[b,m] = sum over nnz entries of col m:
//   val * A[b, k], A = [X | sr*state] (sr folded into A on load).
// A chunk (128 k x 128 b) in smem, transposed, double-buffered.
// 512 threads = 16 warps; warp = 8 cols x 128 b (2 pairs/thread).
// Epilogue: bias + tanh + leaky mix via smem transpose (aliased buffer 0).
// smem stride 132 floats.
// ---------------------------------------------------------------------------
#define ASTR 132
#define SMSZ (2 * 128 * ASTR * 4)

__global__ __launch_bounds__(512, 1) void state_kernel(
    const float* __restrict__ X,
    const float* __restrict__ state,
    const float* __restrict__ bias,
    const float* __restrict__ sr,
    float* __restrict__ out_state)
{
    extern __shared__ float sm[];
    float* A0 = sm;
    float* A1 = sm + 128 * ASTR;

    const int t = threadIdx.x;
    const int w = t >> 5;
    const int lane = t & 31;
    const int u = blockIdx.y;
    const int m0 = blockIdx.x * 128;
    const float srv = sr[u];

    const int lb = t >> 2;          // A-load b row 0..127
    const int lk = (t & 3) * 4;     // A-load k offset base

    ull acc[8][2];
    #pragma unroll
    for (int i = 0; i < 8; i++) { acc[i][0] = 0ull; acc[i][1] = 0ull; }

    float4 av[8];

    auto LOADA = [&](int c) {
        const int kc = c * 128;
        const float* xrow = X + ((size_t)lb * Uu + u) * Dd;
        const float* srow = state + ((size_t)lb * Uu + u) * Nn;
        #pragma unroll
        for (int p = 0; p < 8; ++p) {
            int k = kc + lk + p * 16;
            if (k < Dd) {
                av[p] = *(const float4*)(xrow + k);
            } else {
                float4 v = *(const float4*)(srow + (k - Dd));
                v.x *= srv; v.y *= srv; v.z *= srv; v.w *= srv;
                av[p] = v;
            }
        }
    };
    auto STSA = [&](float* Ab) {
        #pragma unroll
        for (int p = 0; p < 8; ++p) {
            int kr = lk + p * 16;
            Ab[(kr + 0) * ASTR + lb] = av[p].x;
            Ab[(kr + 1) * ASTR + lb] = av[p].y;
            Ab[(kr + 2) * ASTR + lb] = av[p].z;
            Ab[(kr + 3) * ASTR + lb] = av[p].w;
        }
    };

    LOADA(0); STSA(A0);
    __syncthreads();

    for (int c = 0; c < NCH; ++c) {
        float* cur = (c & 1) ? A1 : A0;
        if (c < NCH - 1) LOADA(c + 1);
        const int kc = c * 128;

        #pragma unroll 1
        for (int c8 = 0; c8 < 8; ++c8) {
            const int col = u * Nn + m0 + w * 8 + c8;
            const int* cs = g_cs + col * (NCH + 1);
            int s = __ldg(cs + c);
            int e = __ldg(cs + c + 1);
            const ull* ep = g_ent + (size_t)col * CAP;
            ull a0 = acc[c8][0], a1 = acc[c8][1];
            #pragma unroll 4
            for (int j = s; j < e; ++j) {
                ull entv = __ldg(ep + j);
                int krow = (int)(uint32_t)entv - kc;
                ull bs = pk2(hi32(entv));
                ulonglong2 ap = *(const ulonglong2*)(cur + krow * ASTR + lane * 4);
                a0 = fma2(ap.x, bs, a0);
                a1 = fma2(ap.y, bs, a1);
            }
            acc[c8][0] = a0; acc[c8][1] = a1;
        }

        if (c < NCH - 1) {
            STSA((c & 1) ? A0 : A1);
        }
        __syncthreads();
    }

    // ---- epilogue: transpose through smem (alias over A0), then coalesced out
    float* Cs = sm;   // 128 x 132, fits in A0's footprint
    #pragma unroll
    for (int c8 = 0; c8 < 8; ++c8) {
        int mtL = w * 8 + c8;
        float4 v = { lo32(acc[c8][0]), hi32(acc[c8][0]),
                     lo32(acc[c8][1]), hi32(acc[c8][1]) };
        *(float4*)(Cs + mtL * ASTR + lane * 4) = v;
    }
    __syncthreads();

    #pragma unroll 4
    for (int i = 0; i < 32; ++i) {
        int idx = t + i * 512;
        int m = idx & 127;
        int b = idx >> 7;
        float pre = Cs[m * ASTR + b];
        float lrv = g_lr[b * Uu + u];
        size_t go = ((size_t)b * Uu + u) * Nn + m0 + m;
        float so = state[go];
        float bi = bias[(size_t)u * Nn + m0 + m];
        float h = tanhf(pre + bi);
        out_state[go] = so + lrv * (h - so);
    }
}

// ---------------------------------------------------------------------------
// Kernel 3: output = new_state @ Wout, f32x2 m-pair GEMM (dense Wout).
// BM=128, BN=32, BK=16, K=1024. 256 threads. grid = (Oo/32, Uu) = 128 blocks.
// ---------------------------------------------------------------------------
#define AS_S 132

__global__ __launch_bounds__(256) void out_kernel(
    const float* __restrict__ ns,
    const float* __restrict__ Wout,
    float* __restrict__ out)
{
    __shared__ float As[2][16][AS_S];
    __shared__ float Bs[2][16][32];

    const int t = threadIdx.x;
    const int u = blockIdx.y;
    const int n0 = blockIdx.x * 32;

    const int m4 = (t >> 3) * 4;
    const int n4 = (t & 7) * 4;

    ull acc[2][4];
    #pragma unroll
    for (int p = 0; p < 2; p++)
        #pragma unroll
        for (int j = 0; j < 4; j++) acc[p][j] = 0ull;

    float4 av[2];

    auto LOADA = [&](int kt) {
        #pragma unroll
        for (int r = 0; r < 2; r++) {
            int idx = t + r * 256;
            int m = idx >> 2;
            int k4 = (idx & 3) * 4;
            av[r] = *(const float4*)(ns + ((size_t)m * Uu + u) * Nn + kt * 16 + k4);
        }
    };
    auto STSA = [&](int buf) {
        #pragma unroll
        for (int r = 0; r < 2; r++) {
            int idx = t + r * 256;
            int m = idx >> 2;
            int k4 = (idx & 3) * 4;
            As[buf][k4 + 0][m] = av[r].x;
            As[buf][k4 + 1][m] = av[r].y;
            As[buf][k4 + 2][m] = av[r].z;
            As[buf][k4 + 3][m] = av[r].w;
        }
    };
    auto CPB = [&](int kt, int buf) {
        if (t < 128) {
            int k = t >> 3;
            int c = (t & 7) * 4;
            const float* src = Wout + ((size_t)u * Nn + kt * 16 + k) * Oo + n0 + c;
            uint32_t dst = (uint32_t)__cvta_generic_to_shared(&Bs[buf][k][c]);
            CP16(dst, src);
        }
    };
    auto COMPUTE = [&](int buf) {
        #pragma unroll
        for (int kk = 0; kk < 16; kk++) {
            ulonglong2 al = *(const ulonglong2*)&As[buf][kk][m4];
            ull a[2] = { al.x, al.y };
            float4 bv = *(const float4*)&Bs[buf][kk][n4];
            ull b[4] = { pk2(bv.x), pk2(bv.y), pk2(bv.z), pk2(bv.w) };
            #pragma unroll
            for (int p = 0; p < 2; p++)
                #pragma unroll
                for (int j = 0; j < 4; j++)
                    acc[p][j] = fma2(a[p], b[j], acc[p][j]);
        }
    };

    LOADA(0); CPB(0, 0); CPCOMMIT(); STSA(0);
    CPWAIT0(); __syncthreads();

    for (int kt = 0; kt < 64; kt++) {
        int buf = kt & 1;
        if (kt < 63) { LOADA(kt + 1); CPB(kt + 1, buf ^ 1); CPCOMMIT(); }
        COMPUTE(buf);
        if (kt < 63) {
            STSA(buf ^ 1);
            CPWAIT0(); __syncthreads();
        }
    }

    #pragma unroll
    for (int p = 0; p < 2; p++) {
        #pragma unroll
        for (int h = 0; h < 2; h++) {
            int m = m4 + 2 * p + h;
            float4 res;
            res.x = h ? hi32(acc[p][0]) : lo32(acc[p][0]);
            res.y = h ? hi32(acc[p][1]) : lo32(acc[p][1]);
            res.z = h ? hi32(acc[p][2]) : lo32(acc[p][2]);
            res.w = h ? hi32(acc[p][3]) : lo32(acc[p][3]);
            *(float4*)(out + ((size_t)m * Uu + u) * Oo + n0 + n4) = res;
        }
    }
}

// ---------------------------------------------------------------------------
// Launch. inputs: 0:X 1:state 2:W 3:Win 4:bias 5:Wout 6:sr 7:adaptive_lr 8:temp
// out: [new_state (B*U*N) | output (B*U*O)]
// ---------------------------------------------------------------------------
extern "C" void kernel_launch(void* const* d_in, const int* in_sizes, int n_in,
                              void* d_out, int out_size) {
    const float* X     = (const float*)d_in[0];
    const float* state = (const float*)d_in[1];
    const float* W     = (const float*)d_in[2];
    const float* Win   = (const float*)d_in[3];
    const float* bias  = (const float*)d_in[4];
    const float* Wout  = (const float*)d_in[5];
    const float* sr    = (const float*)d_in[6];
    const float* alr   = (const float*)d_in[7];
    const float* temp  = (const float*)d_in[8];

    float* out_state = (float*)d_out;
    float* out_out   = out_state + (size_t)Bb * Uu * Nn;

    cudaFuncSetAttribute(state_kernel, cudaFuncAttributeMaxDynamicSharedMemorySize, SMSZ);

    prep_kernel<<<Bb, 128>>>(X, alr, temp, W, Win);
    state_kernel<<<dim3(Nn / 128, Uu), 512, SMSZ>>>(X, state, bias, sr, out_state);
    out_kernel<<<dim3(Oo / 32, Uu), 256>>>(out_state, Wout, out_out);
}

// round 7
// speedup vs baseline: 1.0023x; 1.0023x over previous
#include <cuda_runtime.h>
#include <math.h>
#include <stdint.h>

#define Bb 128
#define Uu 16
#define Dd 256
#define Nn 1024
#define Oo 256
#define NCH 10
#define SLOT 64

typedef unsigned long long ull;

__device__ float g_lr[Bb * Uu];
__device__ ull   g_ent[(size_t)Uu * Nn * NCH * SLOT];  // [col][chunk][slot] (val<<32 | krow_local)
__device__ int   g_cnt[Uu * Nn * NCH];                 // [col][chunk]

// ---------------------------------------------------------------------------
// helpers
// ---------------------------------------------------------------------------
__device__ __forceinline__ ull pk2(float x) {
    ull r;
    asm("mov.b64 %0, {%1, %1};" : "=l"(r) : "f"(x));
    return r;
}
__device__ __forceinline__ ull fma2(ull a, ull b, ull c) {
    asm("fma.rn.f32x2 %0, %1, %2, %0;" : "+l"(c) : "l"(a), "l"(b));
    return c;
}
__device__ __forceinline__ float lo32(ull v) { return __uint_as_float((uint32_t)v); }
__device__ __forceinline__ float hi32(ull v) { return __uint_as_float((uint32_t)(v >> 32)); }

#define CP16(dst, src) \
    asm volatile("cp.async.cg.shared.global [%0], [%1], 16;" :: "r"(dst), "l"(src))
#define CPCOMMIT() asm volatile("cp.async.commit_group;" ::: "memory")
#define CPWAIT0()  asm volatile("cp.async.wait_group 0;" ::: "memory")

// ---------------------------------------------------------------------------
// Kernel 1: parallel prep. grid = (8 m-tiles, 11, 16 u), 128 threads.
//  blockIdx.y < 10 : pack chunk c of 128 columns (coalesced scan, smem staging)
//  blockIdx.y == 10: lr softmax for batch b = mt*16 + u
// ---------------------------------------------------------------------------
__global__ __launch_bounds__(128) void prep_kernel(
    const float* __restrict__ X,
    const float* __restrict__ alr,
    const float* __restrict__ temp,
    const float* __restrict__ W,
    const float* __restrict__ Win)
{
    const int t  = threadIdx.x;
    const int mt = blockIdx.x;
    const int c  = blockIdx.y;
    const int u  = blockIdx.z;

    if (c == NCH) {
        // ---- lr for batch b = mt*16 + u : 8 lanes per unit uu
        __shared__ float logits[Uu];
        const int b = mt * Uu + u;
        const int uu = t >> 3;
        const int l8 = t & 7;
        const float* xp = X + (b * Uu + uu) * Dd;
        const float* ap = alr + uu * Dd;
        float s = 0.f;
        #pragma unroll
        for (int d = l8; d < Dd; d += 8) s += xp[d] * ap[d];
        s += __shfl_xor_sync(0xffffffffu, s, 1);
        s += __shfl_xor_sync(0xffffffffu, s, 2);
        s += __shfl_xor_sync(0xffffffffu, s, 4);
        if (l8 == 0) logits[uu] = s / temp[0];
        __syncthreads();
        if (t == 0) {
            float m = -INFINITY;
            #pragma unroll
            for (int i = 0; i < Uu; i++) m = fmaxf(m, logits[i]);
            float e[Uu], denom = 0.f;
            #pragma unroll
            for (int i = 0; i < Uu; i++) { e[i] = __expf(logits[i] - m); denom += e[i]; }
            float inv = 1.f / denom;
            #pragma unroll
            for (int i = 0; i < Uu; i++) g_lr[b * Uu + i] = e[i] * inv;
        }
        return;
    }

    // ---- pack: thread owns column m = mt*128 + t, chunk c (128 k-rows)
    __shared__ ull  stage[128 * SLOT];   // 64KB staging
    __shared__ int  scnt[128];

    const int m = mt * 128 + t;
    const int kb = c * 128;
    ull* st = stage + t * SLOT;

    int cnt = 0;
    #pragma unroll 4
    for (int kk = 0; kk < 128; ++kk) {
        int k = kb + kk;
        float v = (k < Dd)
            ? Win[((size_t)u * Dd + k) * Nn + m]
            : W[((size_t)u * Nn + (k - Dd)) * Nn + m];
        if (v != 0.f && cnt < SLOT) {
            st[cnt] = ((ull)__float_as_uint(v) << 32) | (uint32_t)kk;
            cnt++;
        }
    }
    scnt[t] = cnt;
    g_cnt[(u * Nn + m) * NCH + c] = cnt;
    __syncthreads();

    // coalesced write-out: threads sweep [col][slot]
    const size_t gbase = ((size_t)(u * Nn + mt * 128) * NCH + c) * SLOT;
    #pragma unroll 4
    for (int i = t; i < 128 * SLOT; i += 128) {
        int colL = i >> 6;
        int slot = i & (SLOT - 1);
        if (slot < scnt[colL]) {
            // g_ent index for column (base m-tile + colL), chunk c, slot
            g_ent[gbase + (size_t)colL * NCH * SLOT + slot] = stage[colL * SLOT + slot];
        }
    }
}

// ---------------------------------------------------------------------------
// Kernel 2: sparse state update.
// Block (m-tile 128, u): acc[b,m] = sum entries(val,krow) of col m, chunk c:
//   val * A[b, kb+krow], A = [X | sr*state].
// A chunk (128 k x 128 b) transposed in smem, double-buffered.
// 512 threads = 16 warps; warp = 8 cols x 128 b. Counts hoisted per chunk.
// ---------------------------------------------------------------------------
#define ASTR 132
#define SMSZ (2 * 128 * ASTR * 4)

__global__ __launch_bounds__(512, 1) void state_kernel(
    const float* __restrict__ X,
    const float* __restrict__ state,
    const float* __restrict__ bias,
    const float* __restrict__ sr,
    float* __restrict__ out_state)
{
    extern __shared__ float sm[];
    float* A0 = sm;
    float* A1 = sm + 128 * ASTR;

    const int t = threadIdx.x;
    const int w = t >> 5;
    const int lane = t & 31;
    const int u = blockIdx.y;
    const int m0 = blockIdx.x * 128;
    const float srv = sr[u];

    const int colbase = u * Nn + m0 + w * 8;

    const int lb = t >> 2;
    const int lk = (t & 3) * 4;

    ull acc[8][2];
    #pragma unroll
    for (int i = 0; i < 8; i++) { acc[i][0] = 0ull; acc[i][1] = 0ull; }

    float4 av[8];

    auto LOADA = [&](int c) {
        const int kc = c * 128;
        const float* xrow = X + ((size_t)lb * Uu + u) * Dd;
        const float* srow = state + ((size_t)lb * Uu + u) * Nn;
        #pragma unroll
        for (int p = 0; p < 8; ++p) {
            int k = kc + lk + p * 16;
            if (k < Dd) {
                av[p] = *(const float4*)(xrow + k);
            } else {
                float4 v = *(const float4*)(srow + (k - Dd));
                v.x *= srv; v.y *= srv; v.z *= srv; v.w *= srv;
                av[p] = v;
            }
        }
    };
    auto STSA = [&](float* Ab) {
        #pragma unroll
        for (int p = 0; p < 8; ++p) {
            int kr = lk + p * 16;
            Ab[(kr + 0) * ASTR + lb] = av[p].x;
            Ab[(kr + 1) * ASTR + lb] = av[p].y;
            Ab[(kr + 2) * ASTR + lb] = av[p].z;
            Ab[(kr + 3) * ASTR + lb] = av[p].w;
        }
    };

    LOADA(0); STSA(A0);
    __syncthreads();

    for (int c = 0; c < NCH; ++c) {
        float* cur = (c & 1) ? A1 : A0;
        if (c < NCH - 1) LOADA(c + 1);

        // hoist all 8 column counts (independent LDGs -> one latency)
        int cnts[8];
        #pragma unroll
        for (int c8 = 0; c8 < 8; ++c8)
            cnts[c8] = __ldg(g_cnt + (colbase + c8) * NCH + c);

        #pragma unroll 1
        for (int c8 = 0; c8 < 8; ++c8) {
            const ull* ep = g_ent + ((size_t)(colbase + c8) * NCH + c) * SLOT;
            const int e = cnts[c8];
            ull a0 = acc[c8][0], a1 = acc[c8][1];
            #pragma unroll 8
            for (int j = 0; j < e; ++j) {
                ull entv = __ldg(ep + j);
                int krow = (int)(uint32_t)entv;
                ull bs = pk2(hi32(entv));
                ulonglong2 ap = *(const ulonglong2*)(cur + krow * ASTR + lane * 4);
                a0 = fma2(ap.x, bs, a0);
                a1 = fma2(ap.y, bs, a1);
            }
            acc[c8][0] = a0; acc[c8][1] = a1;
        }

        if (c < NCH - 1) STSA((c & 1) ? A0 : A1);
        __syncthreads();
    }

    // ---- epilogue: transpose through smem (alias over A0), coalesced out
    float* Cs = sm;
    #pragma unroll
    for (int c8 = 0; c8 < 8; ++c8) {
        int mtL = w * 8 + c8;
        float4 v = { lo32(acc[c8][0]), hi32(acc[c8][0]),
                     lo32(acc[c8][1]), hi32(acc[c8][1]) };
        *(float4*)(Cs + mtL * ASTR + lane * 4) = v;
    }
    __syncthreads();

    #pragma unroll 4
    for (int i = 0; i < 32; ++i) {
        int idx = t + i * 512;
        int m = idx & 127;
        int b = idx >> 7;
        float pre = Cs[m * ASTR + b];
        float lrv = g_lr[b * Uu + u];
        size_t go = ((size_t)b * Uu + u) * Nn + m0 + m;
        float so = state[go];
        float bi = bias[(size_t)u * Nn + m0 + m];
        float h = tanhf(pre + bi);
        out_state[go] = so + lrv * (h - so);
    }
}

// ---------------------------------------------------------------------------
// Kernel 3: output = new_state @ Wout, f32x2 m-pair GEMM (dense).
// BM=128, BN=32, BK=16, K=1024. 256 threads. grid = (Oo/32, Uu).
// ---------------------------------------------------------------------------
#define AS_S 132

__global__ __launch_bounds__(256) void out_kernel(
    const float* __restrict__ ns,
    const float* __restrict__ Wout,
    float* __restrict__ out)
{
    __shared__ float As[2][16][AS_S];
    __shared__ float Bs[2][16][32];

    const int t = threadIdx.x;
    const int u = blockIdx.y;
    const int n0 = blockIdx.x * 32;

    const int m4 = (t >> 3) * 4;
    const int n4 = (t & 7) * 4;

    ull acc[2][4];
    #pragma unroll
    for (int p = 0; p < 2; p++)
        #pragma unroll
        for (int j = 0; j < 4; j++) acc[p][j] = 0ull;

    float4 av[2];

    auto LOADA = [&](int kt) {
        #pragma unroll
        for (int r = 0; r < 2; r++) {
            int idx = t + r * 256;
            int m = idx >> 2;
            int k4 = (idx & 3) * 4;
            av[r] = *(const float4*)(ns + ((size_t)m * Uu + u) * Nn + kt * 16 + k4);
        }
    };
    auto STSA = [&](int buf) {
        #pragma unroll
        for (int r = 0; r < 2; r++) {
            int idx = t + r * 256;
            int m = idx >> 2;
            int k4 = (idx & 3) * 4;
            As[buf][k4 + 0][m] = av[r].x;
            As[buf][k4 + 1][m] = av[r].y;
            As[buf][k4 + 2][m] = av[r].z;
            As[buf][k4 + 3][m] = av[r].w;
        }
    };
    auto CPB = [&](int kt, int buf) {
        if (t < 128) {
            int k = t >> 3;
            int cc = (t & 7) * 4;
            const float* src = Wout + ((size_t)u * Nn + kt * 16 + k) * Oo + n0 + cc;
            uint32_t dst = (uint32_t)__cvta_generic_to_shared(&Bs[buf][k][cc]);
            CP16(dst, src);
        }
    };
    auto COMPUTE = [&](int buf) {
        #pragma unroll
        for (int kk = 0; kk < 16; kk++) {
            ulonglong2 al = *(const ulonglong2*)&As[buf][kk][m4];
            ull a[2] = { al.x, al.y };
            float4 bv = *(const float4*)&Bs[buf][kk][n4];
            ull b[4] = { pk2(bv.x), pk2(bv.y), pk2(bv.z), pk2(bv.w) };
            #pragma unroll
            for (int p = 0; p < 2; p++)
                #pragma unroll
                for (int j = 0; j < 4; j++)
                    acc[p][j] = fma2(a[p], b[j], acc[p][j]);
        }
    };

    LOADA(0); CPB(0, 0); CPCOMMIT(); STSA(0);
    CPWAIT0(); __syncthreads();

    for (int kt = 0; kt < 64; kt++) {
        int buf = kt & 1;
        if (kt < 63) { LOADA(kt + 1); CPB(kt + 1, buf ^ 1); CPCOMMIT(); }
        COMPUTE(buf);
        if (kt < 63) {
            STSA(buf ^ 1);
            CPWAIT0(); __syncthreads();
        }
    }

    #pragma unroll
    for (int p = 0; p < 2; p++) {
        #pragma unroll
        for (int h = 0; h < 2; h++) {
            int m = m4 + 2 * p + h;
            float4 res;
            res.x = h ? hi32(acc[p][0]) : lo32(acc[p][0]);
            res.y = h ? hi32(acc[p][1]) : lo32(acc[p][1]);
            res.z = h ? hi32(acc[p][2]) : lo32(acc[p][2]);
            res.w = h ? hi32(acc[p][3]) : lo32(acc[p][3]);
            *(float4*)(out + ((size_t)m * Uu + u) * Oo + n0 + n4) = res;
        }
    }
}

// ---------------------------------------------------------------------------
// Launch. inputs: 0:X 1:state 2:W 3:Win 4:bias 5:Wout 6:sr 7:adaptive_lr 8:temp
// out: [new_state (B*U*N) | output (B*U*O)]
// ---------------------------------------------------------------------------
extern "C" void kernel_launch(void* const* d_in, const int* in_sizes, int n_in,
                              void* d_out, int out_size) {
    const float* X     = (const float*)d_in[0];
    const float* state = (const float*)d_in[1];
    const float* W     = (const float*)d_in[2];
    const float* Win   = (const float*)d_in[3];
    const float* bias  = (const float*)d_in[4];
    const float* Wout  = (const float*)d_in[5];
    const float* sr    = (const float*)d_in[6];
    const float* alr   = (const float*)d_in[7];
    const float* temp  = (const float*)d_in[8];

    float* out_state = (float*)d_out;
    float* out_out   = out_state + (size_t)Bb * Uu * Nn;

    cudaFuncSetAttribute(state_kernel, cudaFuncAttributeMaxDynamicSharedMemorySize, SMSZ);

    prep_kernel<<<dim3(8, NCH + 1, Uu), 128>>>(X, alr, temp, W, Win);
    state_kernel<<<dim3(Nn / 128, Uu), 512, SMSZ>>>(X, state, bias, sr, out_state);
    out_kernel<<<dim3(Oo / 32, Uu), 256>>>(out_state, Wout, out_out);
}

// round 8
// speedup vs baseline: 2.1016x; 2.0967x over previous
#include <cuda_runtime.h>
#include <math.h>
#include <stdint.h>

#define Bb 128
#define Uu 16
#define Dd 256
#define Nn 1024
#define Oo 256

typedef unsigned long long ull;

__device__ float g_lr[Bb * Uu];

// ---------------------------------------------------------------------------
// f32x2 helpers
// ---------------------------------------------------------------------------
__device__ __forceinline__ ull pk2(float x) {
    ull r;
    asm("mov.b64 %0, {%1, %1};" : "=l"(r) : "f"(x));
    return r;
}
__device__ __forceinline__ ull fma2(ull a, ull b, ull c) {
    asm("fma.rn.f32x2 %0, %1, %2, %0;" : "+l"(c) : "l"(a), "l"(b));
    return c;
}
__device__ __forceinline__ float lo32(ull v) { return __uint_as_float((uint32_t)v); }
__device__ __forceinline__ float hi32(ull v) { return __uint_as_float((uint32_t)(v >> 32)); }

#define CP16(dst, src) \
    asm volatile("cp.async.cg.shared.global [%0], [%1], 16;" :: "r"(dst), "l"(src))
#define CPCOMMIT() asm volatile("cp.async.commit_group;" ::: "memory")
#define CPWAIT0()  asm volatile("cp.async.wait_group 0;" ::: "memory")

// ---------------------------------------------------------------------------
// Kernel 1: lr[b,u] = softmax over u of (X[b,u,:] . alr[u,:]) / T
// ---------------------------------------------------------------------------
__global__ void lr_kernel(const float* __restrict__ X,
                          const float* __restrict__ alr,
                          const float* __restrict__ temp) {
    int b = blockIdx.x;
    int u = threadIdx.x >> 5;
    int lane = threadIdx.x & 31;
    __shared__ float logits[Uu];

    const float4* xp = (const float4*)(X + (b * Uu + u) * Dd);
    const float4* ap = (const float4*)(alr + u * Dd);
    float s = 0.f;
    #pragma unroll
    for (int d = lane; d < Dd / 4; d += 32) {
        float4 xv = xp[d], av = ap[d];
        s += xv.x * av.x + xv.y * av.y + xv.z * av.z + xv.w * av.w;
    }
    #pragma unroll
    for (int off = 16; off; off >>= 1) s += __shfl_xor_sync(0xffffffffu, s, off);
    if (lane == 0) logits[u] = s / temp[0];
    __syncthreads();

    if (threadIdx.x == 0) {
        float m = -INFINITY;
        #pragma unroll
        for (int i = 0; i < Uu; i++) m = fmaxf(m, logits[i]);
        float e[Uu];
        float denom = 0.f;
        #pragma unroll
        for (int i = 0; i < Uu; i++) { e[i] = __expf(logits[i] - m); denom += e[i]; }
        float inv = 1.f / denom;
        #pragma unroll
        for (int i = 0; i < Uu; i++) g_lr[b * Uu + i] = e[i] * inv;
    }
}

// ---------------------------------------------------------------------------
// Kernel 2: state update, f32x2 GEMM.
// Per (n-tile, u): C[128,128] = [X | sr*state] @ [Win ; W], + bias,tanh,mix.
// BM=128, BN=128, BK=16. 512 threads = 16 warps.
// Warp layout: wm = w&7 -> 16 m-rows (mbase=wm*16); wn = w>>3 -> 64 n-cols.
// Thread: 8 m-pairs (warp-broadcast a) x 2 n (lane*2).
// grid = (Nn/128, Uu) = 128 blocks.
// ---------------------------------------------------------------------------
#define AS_S 132

__global__ __launch_bounds__(512) void state_kernel(
    const float* __restrict__ X,
    const float* __restrict__ state,
    const float* __restrict__ W,
    const float* __restrict__ Win,
    const float* __restrict__ bias,
    const float* __restrict__ sr,
    float* __restrict__ out_state)
{
    __shared__ float As[2][16][AS_S];
    __shared__ float Bs[2][16][128];

    const int t = threadIdx.x;
    const int lane = t & 31;
    const int w = t >> 5;
    const int mbase = (w & 7) * 16;       // warp's 16 m-rows
    const int nbase = (w >> 3) * 64;      // warp's 64 n-cols
    const int n2 = lane * 2;              // thread's 2 n within warp-half
    const int u = blockIdx.y;
    const int n0 = blockIdx.x * 128;

    const int am  = t >> 2;               // A-load row 0..127
    const int ak4 = (t & 3) * 4;          // A-load k offset
    const int bk  = t >> 5;               // B-load k row 0..15
    const int bc4 = (t & 31) * 4;         // B-load col

    const float srv = sr[u];

    ull acc[8][2];
    #pragma unroll
    for (int p = 0; p < 8; p++) { acc[p][0] = 0ull; acc[p][1] = 0ull; }

    float4 av;

    auto LOADA = [&](int kt) {
        int k = kt * 16 + ak4;
        if (k < Dd) {
            av = *(const float4*)(X + ((size_t)am * Uu + u) * Dd + k);
        } else {
            av = *(const float4*)(state + ((size_t)am * Uu + u) * Nn + (k - Dd));
            av.x *= srv; av.y *= srv; av.z *= srv; av.w *= srv;
        }
    };
    auto STSA = [&](int buf) {
        As[buf][ak4 + 0][am] = av.x;
        As[buf][ak4 + 1][am] = av.y;
        As[buf][ak4 + 2][am] = av.z;
        As[buf][ak4 + 3][am] = av.w;
    };
    auto CPB = [&](int kt, int buf) {
        int kg = kt * 16 + bk;
        const float* src = (kg < Dd)
            ? (Win + ((size_t)u * Dd + kg) * Nn + n0 + bc4)
            : (W + ((size_t)u * Nn + (kg - Dd)) * Nn + n0 + bc4);
        uint32_t dst = (uint32_t)__cvta_generic_to_shared(&Bs[buf][bk][bc4]);
        CP16(dst, src);
    };
    auto COMPUTE = [&](int buf) {
        #pragma unroll
        for (int kk = 0; kk < 16; kk++) {
            // a: warp's 16 m-floats = 8 natural pairs, broadcast across lanes
            ulonglong2 a01 = *(const ulonglong2*)&As[buf][kk][mbase];
            ulonglong2 a23 = *(const ulonglong2*)&As[buf][kk][mbase + 4];
            ulonglong2 a45 = *(const ulonglong2*)&As[buf][kk][mbase + 8];
            ulonglong2 a67 = *(const ulonglong2*)&As[buf][kk][mbase + 12];
            ull a[8] = { a01.x, a01.y, a23.x, a23.y, a45.x, a45.y, a67.x, a67.y };
            float2 bv = *(const float2*)&Bs[buf][kk][nbase + n2];
            ull b0 = pk2(bv.x);
            ull b1 = pk2(bv.y);
            #pragma unroll
            for (int p = 0; p < 8; p++) {
                acc[p][0] = fma2(a[p], b0, acc[p][0]);
                acc[p][1] = fma2(a[p], b1, acc[p][1]);
            }
        }
    };

    LOADA(0); CPB(0, 0); CPCOMMIT(); STSA(0);
    CPWAIT0(); __syncthreads();

    for (int kt = 0; kt < 80; kt++) {
        int buf = kt & 1;
        if (kt < 79) { LOADA(kt + 1); CPB(kt + 1, buf ^ 1); CPCOMMIT(); }
        COMPUTE(buf);
        if (kt < 79) {
            STSA(buf ^ 1);
            CPWAIT0(); __syncthreads();
        }
    }

    // epilogue: bias + tanh + leaky mix.
    // acc[p][j]: lo = row mbase+2p, hi = row mbase+2p+1, col n0+nbase+n2+j
    const size_t ncol = (size_t)n0 + nbase + n2;
    float2 bi = *(const float2*)(bias + (size_t)u * Nn + ncol);
    #pragma unroll
    for (int p = 0; p < 8; p++) {
        #pragma unroll
        for (int h = 0; h < 2; h++) {
            int m = mbase + 2 * p + h;
            float c0 = h ? hi32(acc[p][0]) : lo32(acc[p][0]);
            float c1 = h ? hi32(acc[p][1]) : lo32(acc[p][1]);
            float lrv = g_lr[m * Uu + u];
            size_t ro = ((size_t)m * Uu + u) * Nn + ncol;
            float2 so = *(const float2*)(state + ro);
            float2 res;
            res.x = so.x + lrv * (tanhf(c0 + bi.x) - so.x);
            res.y = so.y + lrv * (tanhf(c1 + bi.y) - so.y);
            *(float2*)(out_state + ro) = res;
        }
    }
}

// ---------------------------------------------------------------------------
// Kernel 3: output = new_state @ Wout, f32x2 GEMM.
// BM=64, BN=64, BK=16, K=1024. 256 threads = 8 warps.
// Warp: wm = w&1 -> 32 m (mbase=wm*32); wn = w>>1 -> 16 n (nbase=wn*16).
// Thread: lm = lane>>3 -> 8 m (4 pairs, 8-lane shared a); ln = (lane&7)*2.
// grid = (Oo/64, Bb/64, Uu) = 128 blocks.
// ---------------------------------------------------------------------------
#define OS_S 68

__global__ __launch_bounds__(256) void out_kernel(
    const float* __restrict__ ns,
    const float* __restrict__ Wout,
    float* __restrict__ out)
{
    __shared__ float As[2][16][OS_S];
    __shared__ float Bs[2][16][64];

    const int t = threadIdx.x;
    const int lane = t & 31;
    const int w = t >> 5;
    const int moct = (w & 1) * 32 + (lane >> 3) * 8;  // thread's 8 m-rows
    const int ncol = (w >> 1) * 16 + (lane & 7) * 2;  // thread's 2 n-cols
    const int u = blockIdx.z;
    const int m0 = blockIdx.y * 64;
    const int n0 = blockIdx.x * 64;

    const int am  = t >> 2;         // 0..63
    const int ak4 = (t & 3) * 4;
    const int bk  = t >> 4;         // 0..15
    const int bc4 = (t & 15) * 4;

    ull acc[4][2];
    #pragma unroll
    for (int p = 0; p < 4; p++) { acc[p][0] = 0ull; acc[p][1] = 0ull; }

    float4 av;

    auto LOADA = [&](int kt) {
        av = *(const float4*)(ns + ((size_t)(m0 + am) * Uu + u) * Nn + kt * 16 + ak4);
    };
    auto STSA = [&](int buf) {
        As[buf][ak4 + 0][am] = av.x;
        As[buf][ak4 + 1][am] = av.y;
        As[buf][ak4 + 2][am] = av.z;
        As[buf][ak4 + 3][am] = av.w;
    };
    auto CPB = [&](int kt, int buf) {
        int kg = kt * 16 + bk;
        const float* src = Wout + ((size_t)u * Nn + kg) * Oo + n0 + bc4;
        uint32_t dst = (uint32_t)__cvta_generic_to_shared(&Bs[buf][bk][bc4]);
        CP16(dst, src);
    };
    auto COMPUTE = [&](int buf) {
        #pragma unroll
        for (int kk = 0; kk < 16; kk++) {
            ulonglong2 a01 = *(const ulonglong2*)&As[buf][kk][moct];
            ulonglong2 a23 = *(const ulonglong2*)&As[buf][kk][moct + 4];
            ull a[4] = { a01.x, a01.y, a23.x, a23.y };
            float2 bv = *(const float2*)&Bs[buf][kk][ncol];
            ull b0 = pk2(bv.x);
            ull b1 = pk2(bv.y);
            #pragma unroll
            for (int p = 0; p < 4; p++) {
                acc[p][0] = fma2(a[p], b0, acc[p][0]);
                acc[p][1] = fma2(a[p], b1, acc[p][1]);
            }
        }
    };

    LOADA(0); CPB(0, 0); CPCOMMIT(); STSA(0);
    CPWAIT0(); __syncthreads();

    for (int kt = 0; kt < 64; kt++) {
        int buf = kt & 1;
        if (kt < 63) { LOADA(kt + 1); CPB(kt + 1, buf ^ 1); CPCOMMIT(); }
        COMPUTE(buf);
        if (kt < 63) {
            STSA(buf ^ 1);
            CPWAIT0(); __syncthreads();
        }
    }

    #pragma unroll
    for (int p = 0; p < 4; p++) {
        #pragma unroll
        for (int h = 0; h < 2; h++) {
            int m = m0 + moct + 2 * p + h;
            float2 res;
            res.x = h ? hi32(acc[p][0]) : lo32(acc[p][0]);
            res.y = h ? hi32(acc[p][1]) : lo32(acc[p][1]);
            *(float2*)(out + ((size_t)m * Uu + u) * Oo + n0 + ncol) = res;
        }
    }
}

// ---------------------------------------------------------------------------
// Launch. inputs: 0:X 1:state 2:W 3:Win 4:bias 5:Wout 6:sr 7:adaptive_lr 8:temp
// out: [new_state (B*U*N) | output (B*U*O)]
// ---------------------------------------------------------------------------
extern "C" void kernel_launch(void* const* d_in, const int* in_sizes, int n_in,
                              void* d_out, int out_size) {
    const float* X     = (const float*)d_in[0];
    const float* state = (const float*)d_in[1];
    const float* W     = (const float*)d_in[2];
    const float* Win   = (const float*)d_in[3];
    const float* bias  = (const float*)d_in[4];
    const float* Wout  = (const float*)d_in[5];
    const float* sr    = (const float*)d_in[6];
    const float* alr   = (const float*)d_in[7];
    const float* temp  = (const float*)d_in[8];

    float* out_state = (float*)d_out;
    float* out_out   = out_state + (size_t)Bb * Uu * Nn;

    lr_kernel<<<Bb, 512>>>(X, alr, temp);
    state_kernel<<<dim3(Nn / 128, Uu), 512>>>(X, state, W, Win, bias, sr, out_state);
    out_kernel<<<dim3(Oo / 64, Bb / 64, Uu), 256>>>(out_state, Wout, out_out);
}

// round 11
// speedup vs baseline: 4.2711x; 2.0323x over previous
#include <cuda_runtime.h>
#include <cuda_fp16.h>
#include <math.h>
#include <stdint.h>

#define Bb 128
#define Uu 16
#define Dd 256
#define Nn 1024
#define Oo 256

__device__ float g_lr[Bb * Uu];

// ---------------------------------------------------------------------------
// helpers
// ---------------------------------------------------------------------------
__device__ __forceinline__ uint32_t sptr(const void* p) {
    return (uint32_t)__cvta_generic_to_shared(p);
}

__device__ __forceinline__ void ldmA(uint32_t* r, uint32_t addr) {
    asm volatile("ldmatrix.sync.aligned.m8n8.x4.shared.b16 {%0,%1,%2,%3}, [%4];"
                 : "=r"(r[0]), "=r"(r[1]), "=r"(r[2]), "=r"(r[3]) : "r"(addr));
}
__device__ __forceinline__ void ldmBT(uint32_t* r, uint32_t addr) {
    asm volatile("ldmatrix.sync.aligned.m8n8.x4.trans.shared.b16 {%0,%1,%2,%3}, [%4];"
                 : "=r"(r[0]), "=r"(r[1]), "=r"(r[2]), "=r"(r[3]) : "r"(addr));
}
__device__ __forceinline__ void mma16816(float* c, const uint32_t* a, const uint32_t* b) {
    asm volatile(
        "mma.sync.aligned.m16n8k16.row.col.f32.f16.f16.f32 "
        "{%0,%1,%2,%3},{%4,%5,%6,%7},{%8,%9},{%0,%1,%2,%3};"
        : "+f"(c[0]), "+f"(c[1]), "+f"(c[2]), "+f"(c[3])
        : "r"(a[0]), "r"(a[1]), "r"(a[2]), "r"(a[3]), "r"(b[0]), "r"(b[1]));
}
__device__ __forceinline__ uint32_t h2pack(float x, float y) {
    __half2 h = __floats2half2_rn(x, y);
    return *(uint32_t*)&h;
}

// ---------------------------------------------------------------------------
// Kernel 1: lr softmax
// ---------------------------------------------------------------------------
__global__ void lr_kernel(const float* __restrict__ X,
                          const float* __restrict__ alr,
                          const float* __restrict__ temp) {
    int b = blockIdx.x;
    int u = threadIdx.x >> 5;
    int lane = threadIdx.x & 31;
    __shared__ float logits[Uu];

    const float4* xp = (const float4*)(X + (b * Uu + u) * Dd);
    const float4* ap = (const float4*)(alr + u * Dd);
    float s = 0.f;
    #pragma unroll
    for (int d = lane; d < Dd / 4; d += 32) {
        float4 xv = xp[d], av = ap[d];
        s += xv.x * av.x + xv.y * av.y + xv.z * av.z + xv.w * av.w;
    }
    #pragma unroll
    for (int off = 16; off; off >>= 1) s += __shfl_xor_sync(0xffffffffu, s, off);
    if (lane == 0) logits[u] = s / temp[0];
    __syncthreads();

    if (threadIdx.x == 0) {
        float m = -INFINITY;
        #pragma unroll
        for (int i = 0; i < Uu; i++) m = fmaxf(m, logits[i]);
        float e[Uu], denom = 0.f;
        #pragma unroll
        for (int i = 0; i < Uu; i++) { e[i] = __expf(logits[i] - m); denom += e[i]; }
        float inv = 1.f / denom;
        #pragma unroll
        for (int i = 0; i < Uu; i++) g_lr[b * Uu + i] = e[i] * inv;
    }
}

// ---------------------------------------------------------------------------
// Kernel 2: state update via fp16 HMMA (m16n8k16), fp32 accum.
// Per (n-tile, u): C[128,128] = [X | sr*state] @ [Win ; W] + bias,tanh,mix.
// BM=128, BN=128, BK=32. 256 threads = 8 warps (2m x 4n); warp 64m x 32n.
// A smem [m][k] fp16, row stride 40 halves (80B). B smem [k][n] fp16,
// row stride 136 halves (272B), B-fragments via ldmatrix.x4.trans.
// grid = (Nn/128, Uu) = 128 blocks.
// ---------------------------------------------------------------------------
#define ASTRH 40
#define BSTRH 136

__global__ __launch_bounds__(256) void state_kernel(
    const float* __restrict__ X,
    const float* __restrict__ state,
    const float* __restrict__ W,
    const float* __restrict__ Win,
    const float* __restrict__ bias,
    const float* __restrict__ sr,
    float* __restrict__ out_state)
{
    __shared__ __half As[2][128 * ASTRH];
    __shared__ __half Bs[2][32 * BSTRH];

    const int t = threadIdx.x;
    const int lane = t & 31;
    const int w = t >> 5;
    const int mw = (w & 1) * 64;       // warp m-offset
    const int nw = (w >> 1) * 32;      // warp n-offset
    const int u = blockIdx.y;
    const int n0 = blockIdx.x * 128;
    const float srv = sr[u];

    // A staging: thread -> (m = t>>1, khalf = (t&1)*16), 16 k-elems
    const int am = t >> 1;
    const int akh = (t & 1) * 16;
    // B staging: thread -> (k = t>>3, n16 = (t&7)*16), 16 n-elems
    const int bk = t >> 3;
    const int bn = (t & 7) * 16;

    float acc[4][4][4];   // [mt][nt][c]
    #pragma unroll
    for (int i = 0; i < 4; i++)
        #pragma unroll
        for (int j = 0; j < 4; j++)
            #pragma unroll
            for (int c = 0; c < 4; c++) acc[i][j][c] = 0.f;

    float4 ar[4], br[4];

    auto LOADG = [&](int kt) {
        const int kb = kt * 32;
        // A: 16 consecutive k from X or state row am
        {
            int k = kb + akh;
            const float4* src = (k < Dd)
                ? (const float4*)(X + ((size_t)am * Uu + u) * Dd + k)
                : (const float4*)(state + ((size_t)am * Uu + u) * Nn + (k - Dd));
            #pragma unroll
            for (int i = 0; i < 4; i++) ar[i] = src[i];
            if (k >= Dd) {
                #pragma unroll
                for (int i = 0; i < 4; i++) {
                    ar[i].x *= srv; ar[i].y *= srv; ar[i].z *= srv; ar[i].w *= srv;
                }
            }
        }
        // B: 16 consecutive n from row (kb + bk) of Win/W
        {
            int kg = kb + bk;
            const float4* src = (kg < Dd)
                ? (const float4*)(Win + ((size_t)u * Dd + kg) * Nn + n0 + bn)
                : (const float4*)(W + ((size_t)u * Nn + (kg - Dd)) * Nn + n0 + bn);
            #pragma unroll
            for (int i = 0; i < 4; i++) br[i] = src[i];
        }
    };
    auto STS = [&](int buf) {
        {
            uint32_t pk[8];
            #pragma unroll
            for (int i = 0; i < 4; i++) {
                pk[2*i]   = h2pack(ar[i].x, ar[i].y);
                pk[2*i+1] = h2pack(ar[i].z, ar[i].w);
            }
            uint4* dst = (uint4*)&As[buf][am * ASTRH + akh];
            dst[0] = make_uint4(pk[0], pk[1], pk[2], pk[3]);
            dst[1] = make_uint4(pk[4], pk[5], pk[6], pk[7]);
        }
        {
            uint32_t pk[8];
            #pragma unroll
            for (int i = 0; i < 4; i++) {
                pk[2*i]   = h2pack(br[i].x, br[i].y);
                pk[2*i+1] = h2pack(br[i].z, br[i].w);
            }
            uint4* dst = (uint4*)&Bs[buf][bk * BSTRH + bn];
            dst[0] = make_uint4(pk[0], pk[1], pk[2], pk[3]);
            dst[1] = make_uint4(pk[4], pk[5], pk[6], pk[7]);
        }
    };
    auto COMPUTE = [&](int buf) {
        #pragma unroll
        for (int ks = 0; ks < 2; ks++) {
            const int kc = ks * 16;
            // A fragments: 4 m-tiles
            uint32_t af[4][4];
            {
                int i = lane & 7, grp = lane >> 3;
                int mrow = (grp & 1) * 8 + i;
                int kcol = kc + (grp >> 1) * 8;
                #pragma unroll
                for (int mt = 0; mt < 4; mt++) {
                    uint32_t addr = sptr(&As[buf][(mw + mt * 16 + mrow) * ASTRH + kcol]);
                    ldmA(af[mt], addr);
                }
            }
            // B fragments: 4 n-tiles via 2 x ldmatrix.x4.trans
            uint32_t bf[4][2];
            {
                int i = lane & 7, grp = lane >> 3;
                // x4.trans tile order: (k0-7,nA),(k8-15,nA),(k0-7,nB),(k8-15,nB)
                #pragma unroll
                for (int pair = 0; pair < 2; pair++) {
                    int nA = nw + pair * 16;
                    int krow = kc + (grp & 1) * 8 + i;
                    int ncol = nA + (grp >> 1) * 8;
                    uint32_t addr = sptr(&Bs[buf][krow * BSTRH + ncol]);
                    uint32_t r[4];
                    ldmBT(r, addr);
                    bf[pair * 2 + 0][0] = r[0]; bf[pair * 2 + 0][1] = r[1];
                    bf[pair * 2 + 1][0] = r[2]; bf[pair * 2 + 1][1] = r[3];
                }
            }
            #pragma unroll
            for (int mt = 0; mt < 4; mt++)
                #pragma unroll
                for (int nt = 0; nt < 4; nt++)
                    mma16816(acc[mt][nt], af[mt], bf[nt]);
        }
    };

    LOADG(0); STS(0);
    __syncthreads();

    for (int kt = 0; kt < 40; kt++) {
        int buf = kt & 1;
        if (kt < 39) LOADG(kt + 1);
        COMPUTE(buf);
        if (kt < 39) STS(buf ^ 1);
        __syncthreads();
    }

    // epilogue: bias + tanh + leaky mix.
    // c0,c1 -> (m = base + lane>>2, n = nbase + (lane&3)*2, +1); c2,c3 -> m+8
    #pragma unroll
    for (int mt = 0; mt < 4; mt++) {
        #pragma unroll
        for (int half = 0; half < 2; half++) {
            int m = mw + mt * 16 + half * 8 + (lane >> 2);
            float lrv = g_lr[m * Uu + u];
            #pragma unroll
            for (int nt = 0; nt < 4; nt++) {
                int n = n0 + nw + nt * 8 + (lane & 3) * 2;
                float c0 = acc[mt][nt][half * 2 + 0];
                float c1 = acc[mt][nt][half * 2 + 1];
                size_t ro = ((size_t)m * Uu + u) * Nn + n;
                float2 so = *(const float2*)(state + ro);
                float2 bi = *(const float2*)(bias + (size_t)u * Nn + n);
                float2 res;
                res.x = so.x + lrv * (tanhf(c0 + bi.x) - so.x);
                res.y = so.y + lrv * (tanhf(c1 + bi.y) - so.y);
                *(float2*)(out_state + ro) = res;
            }
        }
    }
}

// ---------------------------------------------------------------------------
// Kernel 3: output = new_state @ Wout via fp16 HMMA.
// BM=64, BN=64, BK=32, K=1024. 128 threads = 4 warps (2m x 2n); warp 32m x 32n.
// grid = (Oo/64, Bb/64, Uu) = 128 blocks.
// ---------------------------------------------------------------------------
__global__ __launch_bounds__(128) void out_kernel(
    const float* __restrict__ ns,
    const float* __restrict__ Wout,
    float* __restrict__ out)
{
    __shared__ __half As[2][64 * ASTRH];
    __shared__ __half Bs[2][32 * BSTRH];   // only 64 n used per row

    const int t = threadIdx.x;
    const int lane = t & 31;
    const int w = t >> 5;
    const int mw = (w & 1) * 32;
    const int nw = (w >> 1) * 32;
    const int u = blockIdx.z;
    const int m0 = blockIdx.y * 64;
    const int n0 = blockIdx.x * 64;

    const int am = t >> 1;             // 0..63
    const int akh = (t & 1) * 16;
    const int bk = t >> 2;             // 0..31
    const int bn = (t & 3) * 16;

    float acc[2][4][4];
    #pragma unroll
    for (int i = 0; i < 2; i++)
        #pragma unroll
        for (int j = 0; j < 4; j++)
            #pragma unroll
            for (int c = 0; c < 4; c++) acc[i][j][c] = 0.f;

    float4 ar[4], br[4];

    auto LOADG = [&](int kt) {
        const int kb = kt * 32;
        {
            const float4* src = (const float4*)(ns + ((size_t)(m0 + am) * Uu + u) * Nn + kb + akh);
            #pragma unroll
            for (int i = 0; i < 4; i++) ar[i] = src[i];
        }
        {
            const float4* src = (const float4*)(Wout + ((size_t)u * Nn + kb + bk) * Oo + n0 + bn);
            #pragma unroll
            for (int i = 0; i < 4; i++) br[i] = src[i];
        }
    };
    auto STS = [&](int buf) {
        {
            uint32_t pk[8];
            #pragma unroll
            for (int i = 0; i < 4; i++) {
                pk[2*i]   = h2pack(ar[i].x, ar[i].y);
                pk[2*i+1] = h2pack(ar[i].z, ar[i].w);
            }
            uint4* dst = (uint4*)&As[buf][am * ASTRH + akh];
            dst[0] = make_uint4(pk[0], pk[1], pk[2], pk[3]);
            dst[1] = make_uint4(pk[4], pk[5], pk[6], pk[7]);
        }
        {
            uint32_t pk[8];
            #pragma unroll
            for (int i = 0; i < 4; i++) {
                pk[2*i]   = h2pack(br[i].x, br[i].y);
                pk[2*i+1] = h2pack(br[i].z, br[i].w);
            }
            uint4* dst = (uint4*)&Bs[buf][bk * BSTRH + bn];
            dst[0] = make_uint4(pk[0], pk[1], pk[2], pk[3]);
            dst[1] = make_uint4(pk[4], pk[5], pk[6], pk[7]);
        }
    };
    auto COMPUTE = [&](int buf) {
        #pragma unroll
        for (int ks = 0; ks < 2; ks++) {
            const int kc = ks * 16;
            uint32_t af[2][4];
            {
                int i = lane & 7, grp = lane >> 3;
                int mrow = (grp & 1) * 8 + i;
                int kcol = kc + (grp >> 1) * 8;
                #pragma unroll
                for (int mt = 0; mt < 2; mt++) {
                    uint32_t addr = sptr(&As[buf][(mw + mt * 16 + mrow) * ASTRH + kcol]);
                    ldmA(af[mt], addr);
                }
            }
            uint32_t bf[4][2];
            {
                int i = lane & 7, grp = lane >> 3;
                #pragma unroll
                for (int pair = 0; pair < 2; pair++) {
                    int nA = nw + pair * 16;
                    int krow = kc + (grp & 1) * 8 + i;
                    int ncol = nA + (grp >> 1) * 8;
                    uint32_t addr = sptr(&Bs[buf][krow * BSTRH + ncol]);
                    uint32_t r[4];
                    ldmBT(r, addr);
                    bf[pair * 2 + 0][0] = r[0]; bf[pair * 2 + 0][1] = r[1];
                    bf[pair * 2 + 1][0] = r[2]; bf[pair * 2 + 1][1] = r[3];
                }
            }
            #pragma unroll
            for (int mt = 0; mt < 2; mt++)
                #pragma unroll
                for (int nt = 0; nt < 4; nt++)
                    mma16816(acc[mt][nt], af[mt], bf[nt]);
        }
    };

    LOADG(0); STS(0);
    __syncthreads();

    for (int kt = 0; kt < 32; kt++) {
        int buf = kt & 1;
        if (kt < 31) LOADG(kt + 1);
        COMPUTE(buf);
        if (kt < 31) STS(buf ^ 1);
        __syncthreads();
    }

    #pragma unroll
    for (int mt = 0; mt < 2; mt++) {
        #pragma unroll
        for (int half = 0; half < 2; half++) {
            int m = m0 + mw + mt * 16 + half * 8 + (lane >> 2);
            #pragma unroll
            for (int nt = 0; nt < 4; nt++) {
                int n = n0 + nw + nt * 8 + (lane & 3) * 2;
                float2 res = { acc[mt][nt][half * 2 + 0], acc[mt][nt][half * 2 + 1] };
                *(float2*)(out + ((size_t)m * Uu + u) * Oo + n) = res;
            }
        }
    }
}

// ---------------------------------------------------------------------------
// Launch. inputs: 0:X 1:state 2:W 3:Win 4:bias 5:Wout 6:sr 7:adaptive_lr 8:temp
// ---------------------------------------------------------------------------
extern "C" void kernel_launch(void* const* d_in, const int* in_sizes, int n_in,
                              void* d_out, int out_size) {
    const float* X     = (const float*)d_in[0];
    const float* state = (const float*)d_in[1];
    const float* W     = (const float*)d_in[2];
    const float* Win   = (const float*)d_in[3];
    const float* bias  = (const float*)d_in[4];
    const float* Wout  = (const float*)d_in[5];
    const float* sr    = (const float*)d_in[6];
    const float* alr   = (const float*)d_in[7];
    const float* temp  = (const float*)d_in[8];

    float* out_state = (float*)d_out;
    float* out_out   = out_state + (size_t)Bb * Uu * Nn;

    lr_kernel<<<Bb, 512>>>(X, alr, temp);
    state_kernel<<<dim3(Nn / 128, Uu), 256>>>(X, state, W, Win, bias, sr, out_state);
    out_kernel<<<dim3(Oo / 64, Bb / 64, Uu), 128>>>(out_state, Wout, out_out);
}

// round 12
// speedup vs baseline: 5.5207x; 1.2926x over previous
#include <cuda_runtime.h>
#include <cuda_fp16.h>
#include <math.h>
#include <stdint.h>

#define Bb 128
#define Uu 16
#define Dd 256
#define Nn 1024
#define Oo 256

__device__ float g_lr[Bb * Uu];

// fp16 tile images (uint4 for 16B alignment)
// g_At [u][40kt][128m x 40h]           : state-GEMM A tiles
// g_Bt [u][8nt][40kt][32k x 136h]      : state-GEMM B tiles ([Win;W])
// g_Wt [u][4ot][32kt][32k x 72h]       : out-GEMM B tiles (Wout)
// g_NSt[u][2mt][32kt][64m x 40h]       : out-GEMM A tiles (fp16 new_state)
__device__ uint4 g_At[409600];
__device__ uint4 g_Bt[2785280];
__device__ uint4 g_Wt[589824];
__device__ uint4 g_NSt[327680];

// ---------------------------------------------------------------------------
// helpers
// ---------------------------------------------------------------------------
__device__ __forceinline__ uint32_t sptr(const void* p) {
    return (uint32_t)__cvta_generic_to_shared(p);
}
__device__ __forceinline__ void ldmA(uint32_t* r, uint32_t addr) {
    asm volatile("ldmatrix.sync.aligned.m8n8.x4.shared.b16 {%0,%1,%2,%3}, [%4];"
                 : "=r"(r[0]), "=r"(r[1]), "=r"(r[2]), "=r"(r[3]) : "r"(addr));
}
__device__ __forceinline__ void ldmBT(uint32_t* r, uint32_t addr) {
    asm volatile("ldmatrix.sync.aligned.m8n8.x4.trans.shared.b16 {%0,%1,%2,%3}, [%4];"
                 : "=r"(r[0]), "=r"(r[1]), "=r"(r[2]), "=r"(r[3]) : "r"(addr));
}
__device__ __forceinline__ void mma16816(float* c, const uint32_t* a, const uint32_t* b) {
    asm volatile(
        "mma.sync.aligned.m16n8k16.row.col.f32.f16.f16.f32 "
        "{%0,%1,%2,%3},{%4,%5,%6,%7},{%8,%9},{%0,%1,%2,%3};"
        : "+f"(c[0]), "+f"(c[1]), "+f"(c[2]), "+f"(c[3])
        : "r"(a[0]), "r"(a[1]), "r"(a[2]), "r"(a[3]), "r"(b[0]), "r"(b[1]));
}
__device__ __forceinline__ uint32_t h2pack(float x, float y) {
    __half2 h = __floats2half2_rn(x, y);
    return *(uint32_t*)&h;
}
__device__ __forceinline__ uint4 pack8(float4 a, float4 b) {
    return make_uint4(h2pack(a.x, a.y), h2pack(a.z, a.w),
                      h2pack(b.x, b.y), h2pack(b.z, b.w));
}

#define MBAR_INIT(addr, cnt) \
    asm volatile("mbarrier.init.shared.b64 [%0], %1;" :: "r"(addr), "r"(cnt) : "memory")
#define MBAR_EXPECT_TX(addr, tx) \
    asm volatile("mbarrier.arrive.expect_tx.shared.b64 _, [%0], %1;" :: "r"(addr), "r"(tx) : "memory")
#define MBAR_WAIT(addr, ph) do { \
    uint32_t _m = (addr); uint32_t _p = (ph); uint32_t _d; \
    asm volatile("{\n\t.reg .pred p;\n\t" \
        "mbarrier.try_wait.parity.acquire.cta.shared::cta.b64 p, [%1], %2;\n\t" \
        "selp.b32 %0, 1, 0, p;\n\t}" : "=r"(_d) : "r"(_m), "r"(_p) : "memory"); \
    if (!_d) { \
        asm volatile("{\n\t.reg .pred P1;\n\t" \
            "WL%=:\n\t" \
            "mbarrier.try_wait.parity.acquire.cta.shared::cta.b64 P1, [%0], %1, 0x989680;\n\t" \
            "@P1 bra.uni WD%=;\n\t" \
            "bra.uni WL%=;\n\t" \
            "WD%=:\n\t}" :: "r"(_m), "r"(_p) : "memory"); \
    } } while (0)
#define BULK_G2S(dst, src, bytes, mbar) \
    asm volatile("cp.async.bulk.shared::cta.global.mbarrier::complete_tx::bytes [%0], [%1], %2, [%3];" \
        :: "r"(dst), "l"(src), "r"(bytes), "r"(mbar) : "memory")

// ---------------------------------------------------------------------------
// Kernel 0: prep — fp16 conversion + tile packing (sr folded into state rows)
// ---------------------------------------------------------------------------
__global__ __launch_bounds__(256) void prep_kernel(
    const float* __restrict__ X,
    const float* __restrict__ state,
    const float* __restrict__ W,
    const float* __restrict__ Win,
    const float* __restrict__ Wout,
    const float* __restrict__ sr)
{
    const int tid = blockIdx.x * blockDim.x + threadIdx.x;
    const int nth = gridDim.x * blockDim.x;
    __half* At = (__half*)g_At;
    __half* Bt = (__half*)g_Bt;
    __half* Wt = (__half*)g_Wt;

    // A-X: u,b,k8(32)  -> 65536 items
    for (int i = tid; i < 65536; i += nth) {
        int u = i >> 12, r = i & 4095, b = r >> 5, k8 = r & 31;
        const float4* s = (const float4*)X + ((size_t)(b * Uu + u) * 64 + k8 * 2);
        float4 v0 = s[0], v1 = s[1];
        int k = k8 * 8, kt = k >> 5;
        *(uint4*)(At + ((size_t)(u * 40 + kt)) * 5120 + b * 40 + (k & 31)) = pack8(v0, v1);
    }
    // A-state: u,b,k8(128) -> 262144 items (fold sr)
    for (int i = tid; i < 262144; i += nth) {
        int u = i >> 14, r = i & 16383, b = r >> 7, k8 = r & 127;
        float srv = __ldg(sr + u);
        const float4* s = (const float4*)state + ((size_t)(b * Uu + u) * 256 + k8 * 2);
        float4 v0 = s[0], v1 = s[1];
        v0.x *= srv; v0.y *= srv; v0.z *= srv; v0.w *= srv;
        v1.x *= srv; v1.y *= srv; v1.z *= srv; v1.w *= srv;
        int k = 256 + k8 * 8, kt = k >> 5;
        *(uint4*)(At + ((size_t)(u * 40 + kt)) * 5120 + b * 40 + (k & 31)) = pack8(v0, v1);
    }
    // B-Win: u,krow(256),n8(128) -> 524288 items
    for (int i = tid; i < 524288; i += nth) {
        int u = i >> 15, r = i & 32767, krow = r >> 7, n8 = r & 127;
        const float4* s = (const float4*)Win + ((size_t)(u * Dd + krow) * 256 + n8 * 2);
        float4 v0 = s[0], v1 = s[1];
        int nt = n8 >> 4, kt = krow >> 5;
        *(uint4*)(Bt + ((size_t)((u * 8 + nt) * 40 + kt)) * 4352
                  + (krow & 31) * 136 + (n8 & 15) * 8) = pack8(v0, v1);
    }
    // B-W: u,krow(1024),n8(128) -> 2097152 items
    for (int i = tid; i < 2097152; i += nth) {
        int u = i >> 17, r = i & 131071, krow = r >> 7, n8 = r & 127;
        const float4* s = (const float4*)W + ((size_t)(u * Nn + krow) * 256 + n8 * 2);
        float4 v0 = s[0], v1 = s[1];
        int nt = n8 >> 4, kt = 8 + (krow >> 5);
        *(uint4*)(Bt + ((size_t)((u * 8 + nt) * 40 + kt)) * 4352
                  + (krow & 31) * 136 + (n8 & 15) * 8) = pack8(v0, v1);
    }
    // Wout: u,krow(1024),o8(32) -> 524288 items
    for (int i = tid; i < 524288; i += nth) {
        int u = i >> 15, r = i & 32767, krow = r >> 5, o8 = r & 31;
        const float4* s = (const float4*)Wout + ((size_t)(u * Nn + krow) * 64 + o8 * 2);
        float4 v0 = s[0], v1 = s[1];
        int ot = o8 >> 3, kt = krow >> 5;
        *(uint4*)(Wt + ((size_t)((u * 4 + ot) * 32 + kt)) * 2304
                  + (krow & 31) * 72 + (o8 & 7) * 8) = pack8(v0, v1);
    }
}

// ---------------------------------------------------------------------------
// Kernel 1: lr softmax
// ---------------------------------------------------------------------------
__global__ void lr_kernel(const float* __restrict__ X,
                          const float* __restrict__ alr,
                          const float* __restrict__ temp) {
    int b = blockIdx.x;
    int u = threadIdx.x >> 5;
    int lane = threadIdx.x & 31;
    __shared__ float logits[Uu];

    const float4* xp = (const float4*)(X + (b * Uu + u) * Dd);
    const float4* ap = (const float4*)(alr + u * Dd);
    float s = 0.f;
    #pragma unroll
    for (int d = lane; d < Dd / 4; d += 32) {
        float4 xv = xp[d], av = ap[d];
        s += xv.x * av.x + xv.y * av.y + xv.z * av.z + xv.w * av.w;
    }
    #pragma unroll
    for (int off = 16; off; off >>= 1) s += __shfl_xor_sync(0xffffffffu, s, off);
    if (lane == 0) logits[u] = s / temp[0];
    __syncthreads();

    if (threadIdx.x == 0) {
        float m = -INFINITY;
        #pragma unroll
        for (int i = 0; i < Uu; i++) m = fmaxf(m, logits[i]);
        float e[Uu], denom = 0.f;
        #pragma unroll
        for (int i = 0; i < Uu; i++) { e[i] = __expf(logits[i] - m); denom += e[i]; }
        float inv = 1.f / denom;
        #pragma unroll
        for (int i = 0; i < Uu; i++) g_lr[b * Uu + i] = e[i] * inv;
    }
}

// ---------------------------------------------------------------------------
// Kernel 2: state GEMM via bulk-copy pipeline + HMMA.
// BM=128, BN=128, BK=32, 40 kts, 3-stage. 256 thr = 8 warps (2m x 4n).
// smem: As 3x10240B, Bs 3x8704B, mbar 3x8B  (dynamic, 56880B)
// grid = (8 nt, 16 u)
// ---------------------------------------------------------------------------
#define ST_AB 10240
#define ST_BB 8704
#define ST_AOFF 0
#define ST_BOFF (3 * ST_AB)
#define ST_MOFF (ST_BOFF + 3 * ST_BB)
#define ST_SMEM (ST_MOFF + 48)

__global__ __launch_bounds__(256) void state_kernel(
    const float* __restrict__ state,
    const float* __restrict__ bias,
    float* __restrict__ out_state)
{
    extern __shared__ __align__(16) char smem[];
    const int t = threadIdx.x;
    const int lane = t & 31;
    const int w = t >> 5;
    const int mw = (w & 1) * 64;
    const int nw = (w >> 1) * 32;
    const int u = blockIdx.y;
    const int nt = blockIdx.x;
    const int n0 = nt * 128;

    const uint32_t mb0 = sptr(smem + ST_MOFF);
    if (t == 0) {
        MBAR_INIT(mb0 + 0, 1);
        MBAR_INIT(mb0 + 8, 1);
        MBAR_INIT(mb0 + 16, 1);
    }
    __syncthreads();

    const __half* gA = (const __half*)g_At + (size_t)(u * 40) * 5120;
    const __half* gB = (const __half*)g_Bt + (size_t)((u * 8 + nt) * 40) * 4352;

    auto ISSUE = [&](int kt) {
        int s = kt % 3;
        uint32_t mb = mb0 + s * 8;
        MBAR_EXPECT_TX(mb, ST_AB + ST_BB);
        BULK_G2S(sptr(smem + ST_AOFF + s * ST_AB), gA + (size_t)kt * 5120, ST_AB, mb);
        BULK_G2S(sptr(smem + ST_BOFF + s * ST_BB), gB + (size_t)kt * 4352, ST_BB, mb);
    };

    float acc[4][4][4];
    #pragma unroll
    for (int i = 0; i < 4; i++)
        #pragma unroll
        for (int j = 0; j < 4; j++)
            #pragma unroll
            for (int c = 0; c < 4; c++) acc[i][j][c] = 0.f;

    if (t == 0) { ISSUE(0); ISSUE(1); }

    int ph[3] = {0, 0, 0};
    for (int kt = 0; kt < 40; kt++) {
        int s = kt % 3;
        MBAR_WAIT(mb0 + s * 8, ph[s]);
        ph[s] ^= 1;

        const __half* As = (const __half*)(smem + ST_AOFF + s * ST_AB);
        const __half* Bs = (const __half*)(smem + ST_BOFF + s * ST_BB);
        #pragma unroll
        for (int ks = 0; ks < 2; ks++) {
            const int kc = ks * 16;
            uint32_t af[4][4];
            {
                int i = lane & 7, grp = lane >> 3;
                int mrow = (grp & 1) * 8 + i;
                int kcol = kc + (grp >> 1) * 8;
                #pragma unroll
                for (int mt = 0; mt < 4; mt++)
                    ldmA(af[mt], sptr(As + (mw + mt * 16 + mrow) * 40 + kcol));
            }
            uint32_t bf[4][2];
            {
                int i = lane & 7, grp = lane >> 3;
                #pragma unroll
                for (int pair = 0; pair < 2; pair++) {
                    int krow = kc + (grp & 1) * 8 + i;
                    int ncol = nw + pair * 16 + (grp >> 1) * 8;
                    uint32_t r[4];
                    ldmBT(r, sptr(Bs + krow * 136 + ncol));
                    bf[pair * 2 + 0][0] = r[0]; bf[pair * 2 + 0][1] = r[1];
                    bf[pair * 2 + 1][0] = r[2]; bf[pair * 2 + 1][1] = r[3];
                }
            }
            #pragma unroll
            for (int mt = 0; mt < 4; mt++)
                #pragma unroll
                for (int ntt = 0; ntt < 4; ntt++)
                    mma16816(acc[mt][ntt], af[mt], bf[ntt]);
        }
        __syncthreads();
        if (t == 0 && kt + 2 < 40) ISSUE(kt + 2);
    }

    // epilogue: bias + tanh + leaky mix; also write fp16 tile image for out GEMM
    __half* NSt = (__half*)g_NSt;
    #pragma unroll
    for (int mt = 0; mt < 4; mt++) {
        #pragma unroll
        for (int half = 0; half < 2; half++) {
            int m = mw + mt * 16 + half * 8 + (lane >> 2);
            float lrv = g_lr[m * Uu + u];
            #pragma unroll
            for (int ntt = 0; ntt < 4; ntt++) {
                int n = n0 + nw + ntt * 8 + (lane & 3) * 2;
                float c0 = acc[mt][ntt][half * 2 + 0];
                float c1 = acc[mt][ntt][half * 2 + 1];
                size_t ro = ((size_t)m * Uu + u) * Nn + n;
                float2 so = *(const float2*)(state + ro);
                float2 bi = *(const float2*)(bias + (size_t)u * Nn + n);
                float2 res;
                res.x = so.x + lrv * (tanhf(c0 + bi.x) - so.x);
                res.y = so.y + lrv * (tanhf(c1 + bi.y) - so.y);
                *(float2*)(out_state + ro) = res;
                __half2 h = __floats2half2_rn(res.x, res.y);
                *(__half2*)(NSt + ((size_t)((u * 2 + (m >> 6)) * 32 + (n >> 5))) * 2560
                            + (m & 63) * 40 + (n & 31)) = h;
            }
        }
    }
}

// ---------------------------------------------------------------------------
// Kernel 3: out GEMM via bulk-copy pipeline + HMMA.
// BM=64, BN=64, BK=32, 32 kts, 3-stage. 256 thr = 8 warps (2m x 4n), warp 32x16.
// grid = (4 ot, 2 mt, 16 u)
// ---------------------------------------------------------------------------
__global__ __launch_bounds__(256) void out_kernel(float* __restrict__ out)
{
    __shared__ __align__(16) __half As[3][2560];
    __shared__ __align__(16) __half Bs[3][2304];
    __shared__ __align__(8) unsigned long long mbarr[3];

    const int t = threadIdx.x;
    const int lane = t & 31;
    const int w = t >> 5;
    const int mw = (w & 1) * 32;
    const int nw = (w >> 1) * 16;
    const int u = blockIdx.z;
    const int mt_b = blockIdx.y;
    const int ot = blockIdx.x;
    const int m0 = mt_b * 64;
    const int n0 = ot * 64;

    const uint32_t mb0 = sptr(&mbarr[0]);
    if (t == 0) {
        MBAR_INIT(mb0 + 0, 1);
        MBAR_INIT(mb0 + 8, 1);
        MBAR_INIT(mb0 + 16, 1);
    }
    __syncthreads();

    const __half* gA = (const __half*)g_NSt + (size_t)((u * 2 + mt_b) * 32) * 2560;
    const __half* gB = (const __half*)g_Wt + (size_t)((u * 4 + ot) * 32) * 2304;

    auto ISSUE = [&](int kt) {
        int s = kt % 3;
        uint32_t mb = mb0 + s * 8;
        MBAR_EXPECT_TX(mb, 5120 + 4608);
        BULK_G2S(sptr(&As[s][0]), gA + (size_t)kt * 2560, 5120, mb);
        BULK_G2S(sptr(&Bs[s][0]), gB + (size_t)kt * 2304, 4608, mb);
    };

    float acc[2][2][4];
    #pragma unroll
    for (int i = 0; i < 2; i++)
        #pragma unroll
        for (int j = 0; j < 2; j++)
            #pragma unroll
            for (int c = 0; c < 4; c++) acc[i][j][c] = 0.f;

    if (t == 0) { ISSUE(0); ISSUE(1); }

    int ph[3] = {0, 0, 0};
    for (int kt = 0; kt < 32; kt++) {
        int s = kt % 3;
        MBAR_WAIT(mb0 + s * 8, ph[s]);
        ph[s] ^= 1;

        #pragma unroll
        for (int ks = 0; ks < 2; ks++) {
            const int kc = ks * 16;
            uint32_t af[2][4];
            {
                int i = lane & 7, grp = lane >> 3;
                int mrow = (grp & 1) * 8 + i;
                int kcol = kc + (grp >> 1) * 8;
                #pragma unroll
                for (int mt = 0; mt < 2; mt++)
                    ldmA(af[mt], sptr(&As[s][(mw + mt * 16 + mrow) * 40 + kcol]));
            }
            uint32_t bf[2][2];
            {
                int i = lane & 7, grp = lane >> 3;
                int krow = kc + (grp & 1) * 8 + i;
                int ncol = nw + (grp >> 1) * 8;
                uint32_t r[4];
                ldmBT(r, sptr(&Bs[s][krow * 72 + ncol]));
                bf[0][0] = r[0]; bf[0][1] = r[1];
                bf[1][0] = r[2]; bf[1][1] = r[3];
            }
            #pragma unroll
            for (int mt = 0; mt < 2; mt++)
                #pragma unroll
                for (int ntt = 0; ntt < 2; ntt++)
                    mma16816(acc[mt][ntt], af[mt], bf[ntt]);
        }
        __syncthreads();
        if (t == 0 && kt + 2 < 32) ISSUE(kt + 2);
    }

    #pragma unroll
    for (int mt = 0; mt < 2; mt++) {
        #pragma unroll
        for (int half = 0; half < 2; half++) {
            int m = m0 + mw + mt * 16 + half * 8 + (lane >> 2);
            #pragma unroll
            for (int ntt = 0; ntt < 2; ntt++) {
                int n = n0 + nw + ntt * 8 + (lane & 3) * 2;
                float2 res = { acc[mt][ntt][half * 2 + 0], acc[mt][ntt][half * 2 + 1] };
                *(float2*)(out + ((size_t)m * Uu + u) * Oo + n) = res;
            }
        }
    }
}

// ---------------------------------------------------------------------------
// Launch. inputs: 0:X 1:state 2:W 3:Win 4:bias 5:Wout 6:sr 7:adaptive_lr 8:temp
// ---------------------------------------------------------------------------
extern "C" void kernel_launch(void* const* d_in, const int* in_sizes, int n_in,
                              void* d_out, int out_size) {
    const float* X     = (const float*)d_in[0];
    const float* state = (const float*)d_in[1];
    const float* W     = (const float*)d_in[2];
    const float* Win   = (const float*)d_in[3];
    const float* bias  = (const float*)d_in[4];
    const float* Wout  = (const float*)d_in[5];
    const float* sr    = (const float*)d_in[6];
    const float* alr   = (const float*)d_in[7];
    const float* temp  = (const float*)d_in[8];

    float* out_state = (float*)d_out;
    float* out_out   = out_state + (size_t)Bb * Uu * Nn;

    cudaFuncSetAttribute(state_kernel, cudaFuncAttributeMaxDynamicSharedMemorySize, ST_SMEM);

    prep_kernel<<<1024, 256>>>(X, state, W, Win, Wout, sr);
    lr_kernel<<<Bb, 512>>>(X, alr, temp);
    state_kernel<<<dim3(8, Uu), 256, ST_SMEM>>>(state, bias, out_state);
    out_kernel<<<dim3(4, 2, Uu), 256>>>(out_out);
}

// round 14
// speedup vs baseline: 7.9132x; 1.4334x over previous
#include <cuda_runtime.h>
#include <cuda_fp16.h>
#include <math.h>
#include <stdint.h>

#define Bb 128
#define Uu 16
#define Dd 256
#define Nn 1024
#define Oo 256

__device__ float g_lr[Bb * Uu];

// fp16 tile images
// g_At [u][40kt][128m x 40h]      : state-GEMM A tiles (X | sr*state)
// g_Wt [u][4ot][32kt][32k x 72h]  : out-GEMM B tiles (Wout)
// g_NSt[u][2mt][32kt][64m x 40h]  : out-GEMM A tiles (fp16 new_state)
__device__ uint4 g_At[409600];
__device__ uint4 g_Wt[589824];
__device__ uint4 g_NSt[327680];

// ---------------------------------------------------------------------------
// helpers
// ---------------------------------------------------------------------------
__device__ __forceinline__ uint32_t sptr(const void* p) {
    return (uint32_t)__cvta_generic_to_shared(p);
}
__device__ __forceinline__ void ldmA(uint32_t* r, uint32_t addr) {
    asm volatile("ldmatrix.sync.aligned.m8n8.x4.shared.b16 {%0,%1,%2,%3}, [%4];"
                 : "=r"(r[0]), "=r"(r[1]), "=r"(r[2]), "=r"(r[3]) : "r"(addr));
}
__device__ __forceinline__ void ldmBT(uint32_t* r, uint32_t addr) {
    asm volatile("ldmatrix.sync.aligned.m8n8.x4.trans.shared.b16 {%0,%1,%2,%3}, [%4];"
                 : "=r"(r[0]), "=r"(r[1]), "=r"(r[2]), "=r"(r[3]) : "r"(addr));
}
__device__ __forceinline__ void mma16816(float* c, const uint32_t* a, const uint32_t* b) {
    asm volatile(
        "mma.sync.aligned.m16n8k16.row.col.f32.f16.f16.f32 "
        "{%0,%1,%2,%3},{%4,%5,%6,%7},{%8,%9},{%0,%1,%2,%3};"
        : "+f"(c[0]), "+f"(c[1]), "+f"(c[2]), "+f"(c[3])
        : "r"(a[0]), "r"(a[1]), "r"(a[2]), "r"(a[3]), "r"(b[0]), "r"(b[1]));
}
__device__ __forceinline__ uint32_t h2pack(float x, float y) {
    __half2 h = __floats2half2_rn(x, y);
    return *(uint32_t*)&h;
}
__device__ __forceinline__ uint4 pack8(float4 a, float4 b) {
    return make_uint4(h2pack(a.x, a.y), h2pack(a.z, a.w),
                      h2pack(b.x, b.y), h2pack(b.z, b.w));
}

#define CPA16(dst, src) \
    asm volatile("cp.async.cg.shared.global [%0], [%1], 16;" :: "r"(dst), "l"(src))
#define CPCOMMIT() asm volatile("cp.async.commit_group;" ::: "memory")
#define CPWAIT1()  asm volatile("cp.async.wait_group 1;" ::: "memory")
#define CPWAIT0()  asm volatile("cp.async.wait_group 0;" ::: "memory")

// ---------------------------------------------------------------------------
// Kernel 0: prep (A tiles, Wout tiles) + lr softmax folded in.
// grid.x = 512 convert blocks + 128 lr blocks. 256 threads.
// ---------------------------------------------------------------------------
__global__ __launch_bounds__(256) void prep_kernel(
    const float* __restrict__ X,
    const float* __restrict__ state,
    const float* __restrict__ Wout,
    const float* __restrict__ sr,
    const float* __restrict__ alr,
    const float* __restrict__ temp)
{
    const int t = threadIdx.x;

    if (blockIdx.x >= 512) {
        // ---- lr for batch b
        __shared__ float logits[Uu];
        const int b = blockIdx.x - 512;
        const int u = t >> 4;
        const int l16 = t & 15;
        const float* xp = X + (b * Uu + u) * Dd;
        const float* ap = alr + u * Dd;
        float s = 0.f;
        #pragma unroll
        for (int d = l16; d < Dd; d += 16) s += xp[d] * ap[d];
        #pragma unroll
        for (int off = 1; off < 16; off <<= 1) s += __shfl_xor_sync(0xffffffffu, s, off);
        if (l16 == 0) logits[u] = s / temp[0];
        __syncthreads();
        if (t == 0) {
            float m = -INFINITY;
            #pragma unroll
            for (int i = 0; i < Uu; i++) m = fmaxf(m, logits[i]);
            float e[Uu], denom = 0.f;
            #pragma unroll
            for (int i = 0; i < Uu; i++) { e[i] = __expf(logits[i] - m); denom += e[i]; }
            float inv = 1.f / denom;
            #pragma unroll
            for (int i = 0; i < Uu; i++) g_lr[b * Uu + i] = e[i] * inv;
        }
        return;
    }

    const int tid = blockIdx.x * 256 + t;
    const int nth = 512 * 256;
    __half* At = (__half*)g_At;
    __half* Wt = (__half*)g_Wt;

    // A-X: u,b,k8(32) -> 65536
    for (int i = tid; i < 65536; i += nth) {
        int u = i >> 12, r = i & 4095, b = r >> 5, k8 = r & 31;
        const float4* s = (const float4*)X + ((size_t)(b * Uu + u) * 64 + k8 * 2);
        float4 v0 = s[0], v1 = s[1];
        int k = k8 * 8, kt = k >> 5;
        *(uint4*)(At + ((size_t)(u * 40 + kt)) * 5120 + b * 40 + (k & 31)) = pack8(v0, v1);
    }
    // A-state: u,b,k8(128) -> 262144 (fold sr)
    for (int i = tid; i < 262144; i += nth) {
        int u = i >> 14, r = i & 16383, b = r >> 7, k8 = r & 127;
        float srv = __ldg(sr + u);
        const float4* s = (const float4*)state + ((size_t)(b * Uu + u) * 256 + k8 * 2);
        float4 v0 = s[0], v1 = s[1];
        v0.x *= srv; v0.y *= srv; v0.z *= srv; v0.w *= srv;
        v1.x *= srv; v1.y *= srv; v1.z *= srv; v1.w *= srv;
        int k = 256 + k8 * 8, kt = k >> 5;
        *(uint4*)(At + ((size_t)(u * 40 + kt)) * 5120 + b * 40 + (k & 31)) = pack8(v0, v1);
    }
    // Wout: u,krow(1024),o8(32) -> 524288
    for (int i = tid; i < 524288; i += nth) {
        int u = i >> 15, r = i & 32767, krow = r >> 5, o8 = r & 31;
        const float4* s = (const float4*)Wout + ((size_t)(u * Nn + krow) * 64 + o8 * 2);
        float4 v0 = s[0], v1 = s[1];
        int ot = o8 >> 3, kt = krow >> 5;
        *(uint4*)(Wt + ((size_t)((u * 4 + ot) * 32 + kt)) * 2304
                  + (krow & 31) * 72 + (o8 & 7) * 8) = pack8(v0, v1);
    }
}

// ---------------------------------------------------------------------------
// Kernel 2: state GEMM. A tiles fp16 (g_At) + B fp32 direct (Win/W), inline
// convert to fp16 staging. BM=128, BN=128, BK=32, 40 kts, 3-stage cp.async.
// 256 thr = 8 warps (2m x 4n). grid = (8 nt, 16 u).
// smem: A 3x10240 | F32 3x16896 | F16 2x8704 = 98816 B
// ---------------------------------------------------------------------------
#define SA_OFF   0
#define SF32_OFF 30720
#define SF16_OFF 81408
#define ST_SMEM  98816

__global__ __launch_bounds__(256) void state_kernel(
    const float* __restrict__ state,
    const float* __restrict__ bias,
    const float* __restrict__ W,
    const float* __restrict__ Win,
    float* __restrict__ out_state)
{
    extern __shared__ __align__(16) char smem[];
    const int t = threadIdx.x;
    const int lane = t & 31;
    const int w = t >> 5;
    const int mw = (w & 1) * 64;
    const int nw = (w >> 1) * 32;
    const int u = blockIdx.y;
    const int nt = blockIdx.x;
    const int n0 = nt * 128;

    const __half* gA = (const __half*)g_At + (size_t)(u * 40) * 5120;

    auto ISSUE = [&](int kt) {
        int s = kt % 3;
        // A fp16 tile: 640 x 16B
        char* Asm = smem + SA_OFF + s * 10240;
        const char* gAsrc = (const char*)(gA + (size_t)kt * 5120);
        #pragma unroll
        for (int i = 0; i < 3; i++) {
            int q = t + i * 256;
            if (q < 640) CPA16(sptr(Asm + q * 16), gAsrc + q * 16);
        }
        // B fp32 tile: 32 k-rows x 512B = 1024 x 16B
        char* Bf = smem + SF32_OFF + s * 16896;
        int kg0 = kt * 32;
        const float* bbase = (kg0 < Dd)
            ? (Win + ((size_t)u * Dd + kg0) * Nn + n0)
            : (W + ((size_t)u * Nn + (kg0 - Dd)) * Nn + n0);
        #pragma unroll
        for (int i = 0; i < 4; i++) {
            int q = t + i * 256;
            int r = q >> 5, c16 = q & 31;
            CPA16(sptr(Bf + r * 528 + c16 * 16), (const char*)(bbase + (size_t)r * Nn + c16 * 4));
        }
        CPCOMMIT();
    };

    auto CONVERT = [&](int kt) {
        const char* Bf = smem + SF32_OFF + (kt % 3) * 16896;
        __half* Bh = (__half*)(smem + SF16_OFF + (kt & 1) * 8704);
        #pragma unroll
        for (int i = 0; i < 4; i++) {
            int q = t + i * 256;
            int r = q >> 5, c16 = q & 31;
            float4 v = *(const float4*)(Bf + r * 528 + c16 * 16);
            uint2 p = make_uint2(h2pack(v.x, v.y), h2pack(v.z, v.w));
            *(uint2*)(Bh + r * 136 + c16 * 4) = p;
        }
    };

    float acc[4][4][4];
    #pragma unroll
    for (int i = 0; i < 4; i++)
        #pragma unroll
        for (int j = 0; j < 4; j++)
            #pragma unroll
            for (int c = 0; c < 4; c++) acc[i][j][c] = 0.f;

    ISSUE(0); ISSUE(1);

    for (int kt = 0; kt < 40; kt++) {
        // Tail fix: wait_group 1 does NOT guarantee group kt complete when it
        // is the only outstanding group (last iteration) — drain fully there.
        if (kt + 1 < 40) { CPWAIT1(); } else { CPWAIT0(); }
        __syncthreads();
        CONVERT(kt);
        __syncthreads();
        if (kt + 2 < 40) ISSUE(kt + 2);

        const __half* As = (const __half*)(smem + SA_OFF + (kt % 3) * 10240);
        const __half* Bs = (const __half*)(smem + SF16_OFF + (kt & 1) * 8704);
        #pragma unroll
        for (int ks = 0; ks < 2; ks++) {
            const int kc = ks * 16;
            uint32_t af[4][4];
            {
                int i = lane & 7, grp = lane >> 3;
                int mrow = (grp & 1) * 8 + i;
                int kcol = kc + (grp >> 1) * 8;
                #pragma unroll
                for (int mt = 0; mt < 4; mt++)
                    ldmA(af[mt], sptr(As + (mw + mt * 16 + mrow) * 40 + kcol));
            }
            uint32_t bf[4][2];
            {
                int i = lane & 7, grp = lane >> 3;
                #pragma unroll
                for (int pair = 0; pair < 2; pair++) {
                    int krow = kc + (grp & 1) * 8 + i;
                    int ncol = nw + pair * 16 + (grp >> 1) * 8;
                    uint32_t r[4];
                    ldmBT(r, sptr(Bs + krow * 136 + ncol));
                    bf[pair * 2 + 0][0] = r[0]; bf[pair * 2 + 0][1] = r[1];
                    bf[pair * 2 + 1][0] = r[2]; bf[pair * 2 + 1][1] = r[3];
                }
            }
            #pragma unroll
            for (int mt = 0; mt < 4; mt++)
                #pragma unroll
                for (int ntt = 0; ntt < 4; ntt++)
                    mma16816(acc[mt][ntt], af[mt], bf[ntt]);
        }
    }

    // epilogue: bias + tanh + leaky mix; also write fp16 tile image for out GEMM
    __half* NSt = (__half*)g_NSt;
    #pragma unroll
    for (int mt = 0; mt < 4; mt++) {
        #pragma unroll
        for (int half = 0; half < 2; half++) {
            int m = mw + mt * 16 + half * 8 + (lane >> 2);
            float lrv = g_lr[m * Uu + u];
            #pragma unroll
            for (int ntt = 0; ntt < 4; ntt++) {
                int n = n0 + nw + ntt * 8 + (lane & 3) * 2;
                float c0 = acc[mt][ntt][half * 2 + 0];
                float c1 = acc[mt][ntt][half * 2 + 1];
                size_t ro = ((size_t)m * Uu + u) * Nn + n;
                float2 so = *(const float2*)(state + ro);
                float2 bi = *(const float2*)(bias + (size_t)u * Nn + n);
                float2 res;
                res.x = so.x + lrv * (tanhf(c0 + bi.x) - so.x);
                res.y = so.y + lrv * (tanhf(c1 + bi.y) - so.y);
                *(float2*)(out_state + ro) = res;
                __half2 h = __floats2half2_rn(res.x, res.y);
                *(__half2*)(NSt + ((size_t)((u * 2 + (m >> 6)) * 32 + (n >> 5))) * 2560
                            + (m & 63) * 40 + (n & 31)) = h;
            }
        }
    }
}

// ---------------------------------------------------------------------------
// Kernel 3: out GEMM. BK=64 (2 sub-tiles/stage), 16 iters, 3-stage cp.async.
// BM=64, BN=64. 256 thr = 8 warps (2m x 4n), warp 32x16.
// smem: A 3x10240 | B 3x9216 = 58368 B. grid = (4 ot, 2 mt, 16 u).
// ---------------------------------------------------------------------------
#define OA_OFF 0
#define OB_OFF 30720
#define OT_SMEM 58368

__global__ __launch_bounds__(256) void out_kernel(float* __restrict__ out)
{
    extern __shared__ __align__(16) char smem[];
    const int t = threadIdx.x;
    const int lane = t & 31;
    const int w = t >> 5;
    const int mw = (w & 1) * 32;
    const int nw = (w >> 1) * 16;
    const int u = blockIdx.z;
    const int mt_b = blockIdx.y;
    const int ot = blockIdx.x;
    const int m0 = mt_b * 64;
    const int n0 = ot * 64;

    const char* gA = (const char*)((const __half*)g_NSt + (size_t)((u * 2 + mt_b) * 32) * 2560);
    const char* gB = (const char*)((const __half*)g_Wt + (size_t)((u * 4 + ot) * 32) * 2304);

    auto ISSUE = [&](int it) {
        int s = it % 3;
        char* Asm = smem + OA_OFF + s * 10240;
        char* Bsm = smem + OB_OFF + s * 9216;
        const char* gAsrc = gA + (size_t)it * 10240;
        const char* gBsrc = gB + (size_t)it * 9216;
        #pragma unroll
        for (int i = 0; i < 3; i++) {
            int q = t + i * 256;
            if (q < 640) CPA16(sptr(Asm + q * 16), gAsrc + q * 16);
        }
        #pragma unroll
        for (int i = 0; i < 3; i++) {
            int q = t + i * 256;
            if (q < 576) CPA16(sptr(Bsm + q * 16), gBsrc + q * 16);
        }
        CPCOMMIT();
    };

    float acc[2][2][4];
    #pragma unroll
    for (int i = 0; i < 2; i++)
        #pragma unroll
        for (int j = 0; j < 2; j++)
            #pragma unroll
            for (int c = 0; c < 4; c++) acc[i][j][c] = 0.f;

    ISSUE(0); ISSUE(1);

    for (int it = 0; it < 16; it++) {
        // Tail fix (same wait_group-1 semantics hazard as state_kernel).
        if (it + 1 < 16) { CPWAIT1(); } else { CPWAIT0(); }
        __syncthreads();
        if (it + 2 < 16) ISSUE(it + 2);

        #pragma unroll
        for (int ktl = 0; ktl < 2; ktl++) {
            const __half* As = (const __half*)(smem + OA_OFF + (it % 3) * 10240 + ktl * 5120);
            const __half* Bs = (const __half*)(smem + OB_OFF + (it % 3) * 9216 + ktl * 4608);
            #pragma unroll
            for (int ks = 0; ks < 2; ks++) {
                const int kc = ks * 16;
                uint32_t af[2][4];
                {
                    int i = lane & 7, grp = lane >> 3;
                    int mrow = (grp & 1) * 8 + i;
                    int kcol = kc + (grp >> 1) * 8;
                    #pragma unroll
                    for (int mt = 0; mt < 2; mt++)
                        ldmA(af[mt], sptr(As + (mw + mt * 16 + mrow) * 40 + kcol));
                }
                uint32_t bf[2][2];
                {
                    int i = lane & 7, grp = lane >> 3;
                    int krow = kc + (grp & 1) * 8 + i;
                    int ncol = nw + (grp >> 1) * 8;
                    uint32_t r[4];
                    ldmBT(r, sptr(Bs + krow * 72 + ncol));
                    bf[0][0] = r[0]; bf[0][1] = r[1];
                    bf[1][0] = r[2]; bf[1][1] = r[3];
                }
                #pragma unroll
                for (int mt = 0; mt < 2; mt++)
                    #pragma unroll
                    for (int ntt = 0; ntt < 2; ntt++)
                        mma16816(acc[mt][ntt], af[mt], bf[ntt]);
            }
        }
        __syncthreads();
    }

    #pragma unroll
    for (int mt = 0; mt < 2; mt++) {
        #pragma unroll
        for (int half = 0; half < 2; half++) {
            int m = m0 + mw + mt * 16 + half * 8 + (lane >> 2);
            #pragma unroll
            for (int ntt = 0; ntt < 2; ntt++) {
                int n = n0 + nw + ntt * 8 + (lane & 3) * 2;
                float2 res = { acc[mt][ntt][half * 2 + 0], acc[mt][ntt][half * 2 + 1] };
                *(float2*)(out + ((size_t)m * Uu + u) * Oo + n) = res;
            }
        }
    }
}

// ---------------------------------------------------------------------------
// Launch. inputs: 0:X 1:state 2:W 3:Win 4:bias 5:Wout 6:sr 7:adaptive_lr 8:temp
// ---------------------------------------------------------------------------
extern "C" void kernel_launch(void* const* d_in, const int* in_sizes, int n_in,
                              void* d_out, int out_size) {
    const float* X     = (const float*)d_in[0];
    const float* state = (const float*)d_in[1];
    const float* W     = (const float*)d_in[2];
    const float* Win   = (const float*)d_in[3];
    const float* bias  = (const float*)d_in[4];
    const float* Wout  = (const float*)d_in[5];
    const float* sr    = (const float*)d_in[6];
    const float* alr   = (const float*)d_in[7];
    const float* temp  = (const float*)d_in[8];

    float* out_state = (float*)d_out;
    float* out_out   = out_state + (size_t)Bb * Uu * Nn;

    cudaFuncSetAttribute(state_kernel, cudaFuncAttributeMaxDynamicSharedMemorySize, ST_SMEM);
    cudaFuncSetAttribute(out_kernel,   cudaFuncAttributeMaxDynamicSharedMemorySize, OT_SMEM);

    prep_kernel<<<640, 256>>>(X, state, Wout, sr, alr, temp);
    state_kernel<<<dim3(8, Uu), 256, ST_SMEM>>>(state, bias, W, Win, out_state);
    out_kernel<<<dim3(4, 2, Uu), 256, OT_SMEM>>>(out_out);
}